// round 2
// baseline (speedup 1.0000x reference)
#include <cuda_runtime.h>
#include <math.h>

#define Bz 64
#define Tz 512
#define INz 1024
#define Hz 1024
#define H2z 2048
#define NCTA 128

// Scratch (allocation-free rule: __device__ globals)
__device__ float g_xw[33554432];      // [B*T, H]: x@w_ih^T + b_ih + b_hh
__device__ float g_h[Bz*Hz];          // recurrent state
__device__ float g_hrnn[Bz*Hz];       // tanh output
__device__ float g_p1[8*Bz*Hz];       // split-K partials GEMM1
__device__ float g_p2[8*Bz*H2z];      // split-K partials GEMM2
__device__ unsigned g_count;          // grid barrier arrive counter
__device__ unsigned g_gen;            // grid barrier generation

// ---------------------------------------------------------------------------
// Packed fp32x2 helpers (FFMA2 — only reachable via PTX on sm_103a)
// ---------------------------------------------------------------------------
__device__ __forceinline__ unsigned long long dup2(float a) {
    unsigned long long r;
    asm("mov.b64 %0, {%1, %1};" : "=l"(r) : "f"(a));
    return r;
}
__device__ __forceinline__ void fma2(unsigned long long& acc,
                                     unsigned long long a,
                                     unsigned long long w) {
    asm("fma.rn.f32x2 %0, %1, %2, %0;" : "+l"(acc) : "l"(a), "l"(w));
}

// ---------------------------------------------------------------------------
// Software grid barrier (all NCTA CTAs co-resident: 128 CTAs <= 148 SMs)
// ---------------------------------------------------------------------------
__device__ __forceinline__ void grid_sync() {
    __syncthreads();
    if (threadIdx.x == 0) {
        unsigned g = *(volatile unsigned*)&g_gen;
        __threadfence();
        unsigned old = atomicAdd(&g_count, 1u);
        if (old == NCTA - 1) {
            g_count = 0u;
            __threadfence();
            atomicAdd(&g_gen, 1u);
        } else {
            while (*(volatile unsigned*)&g_gen == g) { }
        }
        __threadfence();
    }
    __syncthreads();
}

// ---------------------------------------------------------------------------
// 64x64 tile GEMM core: C[64, 64] += A[64, kbase:kbase+nK] * W[n0:n0+64, k]^T
// A row-major [64, 1024]; W row-major [N, 1024] (pass W + n0*1024).
// 256 threads, 4x4 register tile packed as 4x2 fp32x2 accumulators.
// ---------------------------------------------------------------------------
__device__ __forceinline__ void gemm_tile(
    float (*As)[68], float (*Ws)[68],
    const float* __restrict__ A, const float* __restrict__ Wt,
    int kbase, int nK, unsigned long long acc[4][2], int tid, bool ldcgA)
{
    const int tx = tid & 15;
    const int ty = tid >> 4;
    for (int kk = 0; kk < nK; kk += 16) {
        #pragma unroll
        for (int i = 0; i < 4; i++) {
            int idx = tid + i * 256;
            int r = idx >> 4, c = idx & 15;
            float av = ldcgA ? __ldcg(&A[r * 1024 + kbase + kk + c])
                             : __ldg (&A[r * 1024 + kbase + kk + c]);
            As[c][r] = av;
            Ws[c][r] = __ldg(&Wt[r * 1024 + kbase + kk + c]);
        }
        __syncthreads();
        #pragma unroll
        for (int k = 0; k < 16; k++) {
            unsigned long long w0 = *reinterpret_cast<const unsigned long long*>(&Ws[k][tx * 4]);
            unsigned long long w1 = *reinterpret_cast<const unsigned long long*>(&Ws[k][tx * 4 + 2]);
            #pragma unroll
            for (int i = 0; i < 4; i++) {
                unsigned long long ad = dup2(As[k][ty * 4 + i]);
                fma2(acc[i][0], ad, w0);
                fma2(acc[i][1], ad, w1);
            }
        }
        __syncthreads();
    }
}

// ---------------------------------------------------------------------------
// Precompute: g_xw[m, n] = x[m,:] . w_ih[n,:] + b_ih[n] + b_hh[n]
// grid (16 n-tiles, 512 m-tiles) — n-tiles contiguous in bid for L2 reuse of x
// ---------------------------------------------------------------------------
__global__ __launch_bounds__(256) void xw_kernel(
    const float* __restrict__ x, const float* __restrict__ w_ih,
    const float* __restrict__ b_ih, const float* __restrict__ b_hh)
{
    __shared__ float As[16][68];
    __shared__ float Ws[16][68];
    const int n0 = blockIdx.x * 64;
    const int m0 = blockIdx.y * 64;
    const int tid = threadIdx.x;
    const int tx = tid & 15;
    const int ty = tid >> 4;
    unsigned long long acc[4][2] = {};

    gemm_tile(As, Ws, x + (size_t)m0 * 1024, w_ih + (size_t)n0 * 1024,
              0, 1024, acc, tid, false);

    #pragma unroll
    for (int i = 0; i < 4; i++) {
        size_t m = m0 + ty * 4 + i;
        #pragma unroll
        for (int jp = 0; jp < 2; jp++) {
            float2 v = *reinterpret_cast<float2*>(&acc[i][jp]);
            int n = n0 + tx * 4 + jp * 2;
            g_xw[m * Hz + n]     = v.x + b_ih[n]     + b_hh[n];
            g_xw[m * Hz + n + 1] = v.y + b_ih[n + 1] + b_hh[n + 1];
        }
    }
}

// ---------------------------------------------------------------------------
// Persistent recurrent kernel: all 512 steps, 128 CTAs, grid barriers.
// ---------------------------------------------------------------------------
__global__ __launch_bounds__(256, 1) void rnn_persistent(
    const float* __restrict__ eps, const float* __restrict__ w_hh,
    const float* __restrict__ w_g, const float* __restrict__ b_g,
    float* __restrict__ o_seq, float* __restrict__ o_prob,
    float* __restrict__ o_mu, float* __restrict__ o_std)
{
    __shared__ float As[16][68];
    __shared__ float Ws[16][68];
    const int cta = blockIdx.x;
    const int tid = threadIdx.x;
    const int tx = tid & 15;
    const int ty = tid >> 4;

    // zero the recurrent state (64*1024 elems / 128 CTAs = 512 each)
    {
        int base = cta * 512;
        g_h[base + tid]       = 0.0f;
        g_h[base + tid + 256] = 0.0f;
    }
    grid_sync();

    for (int t = 0; t < Tz; t++) {
        // ---- Phase 1: GEMM1 split-K partial: g_p1 = h @ w_hh^T ------------
        {
            const int n0 = (cta & 15) * 64;
            const int s  = cta >> 4;          // k-slice 0..7, 128 k each
            unsigned long long acc[4][2] = {};
            gemm_tile(As, Ws, g_h, w_hh + (size_t)n0 * 1024,
                      s * 128, 128, acc, tid, true);
            float* C = g_p1 + (size_t)s * (Bz * Hz);
            #pragma unroll
            for (int i = 0; i < 4; i++) {
                int b = ty * 4 + i;
                #pragma unroll
                for (int jp = 0; jp < 2; jp++) {
                    float2 v = *reinterpret_cast<float2*>(&acc[i][jp]);
                    int n = n0 + tx * 4 + jp * 2;
                    C[b * Hz + n]     = v.x;
                    C[b * Hz + n + 1] = v.y;
                }
            }
        }
        grid_sync();

        // ---- Phase 2: combine partials + xw + tanh -> g_hrnn --------------
        {
            #pragma unroll
            for (int u = 0; u < 2; u++) {
                int idx = cta * 512 + tid + u * 256;   // b*1024 + j
                int b = idx >> 10;
                int j = idx & 1023;
                float v = g_xw[((size_t)b * Tz + t) * Hz + j];
                float p[8];
                #pragma unroll
                for (int s = 0; s < 8; s++)
                    p[s] = __ldcg(&g_p1[(size_t)s * (Bz * Hz) + idx]);
                #pragma unroll
                for (int s = 0; s < 8; s++) v += p[s];
                g_hrnn[idx] = tanhf(v);
            }
        }
        grid_sync();

        // ---- Phase 3: GEMM2 split-K partial: g_p2 = h_rnn @ w_g^T ---------
        {
            #pragma unroll
            for (int w = 0; w < 2; w++) {
                int work = cta * 2 + w;             // 0..255
                int n0 = (work & 31) * 64;
                int s  = work >> 5;                 // 0..7
                unsigned long long acc[4][2] = {};
                gemm_tile(As, Ws, g_hrnn, w_g + (size_t)n0 * 1024,
                          s * 128, 128, acc, tid, true);
                float* C = g_p2 + (size_t)s * (Bz * H2z);
                #pragma unroll
                for (int i = 0; i < 4; i++) {
                    int b = ty * 4 + i;
                    #pragma unroll
                    for (int jp = 0; jp < 2; jp++) {
                        float2 v = *reinterpret_cast<float2*>(&acc[i][jp]);
                        int n = n0 + tx * 4 + jp * 2;
                        C[b * H2z + n]     = v.x;
                        C[b * H2z + n + 1] = v.y;
                    }
                }
            }
        }
        grid_sync();

        // ---- Phase 4: epilogue (CTAs 0..63, one batch row each) -----------
        if (cta < Bz) {
            const int b = cta;
            float lp = 0.0f;
            #pragma unroll
            for (int u = 0; u < 4; u++) {
                int j = tid + u * 256;
                float ss = b_g[j];
                float sm = b_g[Hz + j];
                #pragma unroll
                for (int s = 0; s < 8; s++) {
                    const float* p = g_p2 + (size_t)s * (Bz * H2z) + (size_t)b * H2z;
                    ss += __ldcg(&p[j]);
                    sm += __ldcg(&p[Hz + j]);
                }
                float sd = (ss > 20.0f) ? ss : log1pf(expf(ss));
                float e = eps[((size_t)b * Tz + t) * Hz + j];
                float sample = sm + sd * e;

                size_t o = ((size_t)b * Tz + t) * Hz + j;
                o_seq[o] = sample;
                o_mu[o]  = sm;
                o_std[o] = sd;
                g_h[b * Hz + j] = sample;

                lp += -0.5f * e * e - logf(sd);
            }
            #pragma unroll
            for (int o = 16; o > 0; o >>= 1)
                lp += __shfl_xor_sync(0xffffffffu, lp, o);
            __shared__ float red[8];
            if ((tid & 31) == 0) red[tid >> 5] = lp;
            __syncthreads();
            if (tid == 0) {
                float s = 0.0f;
                #pragma unroll
                for (int w = 0; w < 8; w++) s += red[w];
                o_prob[b * Tz + t] = s - 0.5f * 1.8378770664093453f * (float)Hz;
            }
        }
        grid_sync();
    }
}

// ---------------------------------------------------------------------------
extern "C" void kernel_launch(void* const* d_in, const int* in_sizes, int n_in,
                              void* d_out, int out_size)
{
    const float* x    = (const float*)d_in[0];
    const float* eps  = (const float*)d_in[1];
    const float* w_ih = (const float*)d_in[2];
    const float* w_hh = (const float*)d_in[3];
    const float* b_ih = (const float*)d_in[4];
    const float* b_hh = (const float*)d_in[5];
    const float* w_g  = (const float*)d_in[6];
    const float* b_g  = (const float*)d_in[7];

    float* out = (float*)d_out;
    float* o_seq  = out;                                  // [B,T,H]
    float* o_prob = out + (size_t)Bz * Tz * Hz;           // [B,T]
    float* o_mu   = o_prob + (size_t)Bz * Tz;             // [B,T,H]
    float* o_std  = o_mu + (size_t)Bz * Tz * Hz;          // [B,T,H]

    xw_kernel<<<dim3(16, 512), 256>>>(x, w_ih, b_ih, b_hh);
    rnn_persistent<<<NCTA, 256>>>(eps, w_hh, w_g, b_g,
                                  o_seq, o_prob, o_mu, o_std);
}

// round 3
// speedup vs baseline: 1.5169x; 1.5169x over previous
#include <cuda_runtime.h>
#include <math.h>

#define Bz 64
#define Tz 512
#define Hz 1024
#define H2z 2048
#define NCTA 128
#define NSLC 16            // K slices per GEMM
#define KS 64              // K per slice

// Scratch (__device__ globals; no allocation allowed)
__device__ float g_xw[(size_t)32768 * 1024];   // [B*T, H]
__device__ float g_h[Bz * Hz];
__device__ float g_hrnn[Bz * Hz];
__device__ float g_p1[NSLC * Bz * Hz];
__device__ float g_p2[NSLC * Bz * H2z];
__device__ float g_lpp[Bz][2];
__device__ unsigned g_count, g_gen;

typedef unsigned long long ull;
__device__ __forceinline__ ull dup2(float a) {
    ull r; asm("mov.b64 %0,{%1,%1};" : "=l"(r) : "f"(a)); return r;
}
__device__ __forceinline__ void fma2(ull& acc, ull a, ull w) {
    asm("fma.rn.f32x2 %0,%1,%2,%0;" : "+l"(acc) : "l"(a), "l"(w));
}

struct Smem {
    float As[32][66];     // [k][row], pad 66: staging stores 2-way, reads broadcast
    float Ws[32][130];    // [k][col], pad 130: staging 2-way, reads conflict-free
};

__device__ __forceinline__ void grid_sync() {
    __syncthreads();
    if (threadIdx.x == 0) {
        unsigned g = *(volatile unsigned*)&g_gen;
        __threadfence();
        unsigned old = atomicAdd(&g_count, 1u);
        if (old == NCTA - 1) {
            g_count = 0u;
            __threadfence();
            atomicAdd(&g_gen, 1u);
        } else {
            while (*(volatile unsigned*)&g_gen == g) { }
        }
        __threadfence();
    }
    __syncthreads();
}

// 64x128 output tile: rows = 64 batch, cols = [n0, n0+128) of W's rows.
// A row-major [64][1024]; W row-major (pass W + n0*1024). K window [kb, kb+kcnt).
// Thread (tx=tid&15, ty=tid>>4): rows 4ty..4ty+3, cols {32m + 2tx + p}.
template<bool CG>
__device__ __forceinline__ void gemm_tile(Smem& s,
    const float* __restrict__ A, const float* __restrict__ W,
    int kb, int kcnt, ull acc[4][4])
{
    const int tid = threadIdx.x;
    const int tx = tid & 15;
    const int ty4 = (tid >> 4) << 2;
    for (int k0 = 0; k0 < kcnt; k0 += 32) {
        #pragma unroll
        for (int i = 0; i < 8; i++) {               // A: 64 rows x 32 k
            int e = tid + i * 256;
            int row = e >> 5, kk = e & 31;
            float v = CG ? __ldcg(&A[row * 1024 + kb + k0 + kk])
                         : __ldg (&A[row * 1024 + kb + k0 + kk]);
            s.As[kk][row] = v;
        }
        #pragma unroll
        for (int i = 0; i < 16; i++) {              // W: 128 cols x 32 k
            int e = tid + i * 256;
            int n = e >> 5, kk = e & 31;
            s.Ws[kk][n] = __ldg(&W[n * 1024 + kb + k0 + kk]);
        }
        __syncthreads();
        #pragma unroll 8
        for (int k = 0; k < 32; k++) {
            float2 a01 = *(const float2*)&s.As[k][ty4];
            float2 a23 = *(const float2*)&s.As[k][ty4 + 2];
            ull ad0 = dup2(a01.x), ad1 = dup2(a01.y);
            ull ad2 = dup2(a23.x), ad3 = dup2(a23.y);
            ull w_[4];
            #pragma unroll
            for (int m = 0; m < 4; m++)
                w_[m] = *(const ull*)&s.Ws[k][m * 32 + tx * 2];
            #pragma unroll
            for (int m = 0; m < 4; m++) {
                fma2(acc[0][m], ad0, w_[m]);
                fma2(acc[1][m], ad1, w_[m]);
                fma2(acc[2][m], ad2, w_[m]);
                fma2(acc[3][m], ad3, w_[m]);
            }
        }
        __syncthreads();
    }
}

__device__ __forceinline__ void store_tile(float* __restrict__ Cp, int ldC,
                                           int n0, ull acc[4][4])
{
    const int tid = threadIdx.x;
    const int tx = tid & 15;
    const int ty4 = (tid >> 4) << 2;
    #pragma unroll
    for (int i = 0; i < 4; i++) {
        int b = ty4 + i;
        #pragma unroll
        for (int m = 0; m < 4; m++)
            *(float2*)&Cp[(size_t)b * ldC + n0 + m * 32 + tx * 2] =
                *(float2*)&acc[i][m];
    }
}

// ---------------------------------------------------------------------------
// Precompute: g_xw = x @ w_ih^T + b_ih + b_hh.  grid (8 n-tiles, 512 m-tiles)
// ---------------------------------------------------------------------------
__global__ __launch_bounds__(256) void xw_kernel(
    const float* __restrict__ x, const float* __restrict__ w_ih,
    const float* __restrict__ b_ih, const float* __restrict__ b_hh)
{
    __shared__ Smem s;
    const int n0 = blockIdx.x * 128;
    const int m0 = blockIdx.y * 64;
    const int tid = threadIdx.x;
    const int tx = tid & 15;
    const int ty4 = (tid >> 4) << 2;
    ull acc[4][4] = {};
    gemm_tile<false>(s, x + (size_t)m0 * 1024, w_ih + (size_t)n0 * 1024,
                     0, 1024, acc);
    #pragma unroll
    for (int i = 0; i < 4; i++) {
        size_t m = m0 + ty4 + i;
        #pragma unroll
        for (int m4 = 0; m4 < 4; m4++) {
            int n = n0 + m4 * 32 + tx * 2;
            float2 v = *(float2*)&acc[i][m4];
            v.x += b_ih[n] + b_hh[n];
            v.y += b_ih[n + 1] + b_hh[n + 1];
            *(float2*)&g_xw[m * Hz + n] = v;
        }
    }
}

// ---------------------------------------------------------------------------
// Persistent recurrent kernel: 512 steps, 128 CTAs, 4 grid barriers/step.
// ---------------------------------------------------------------------------
__global__ __launch_bounds__(256, 1) void rnn_persistent(
    const float* __restrict__ eps, const float* __restrict__ w_hh,
    const float* __restrict__ w_g, const float* __restrict__ b_g,
    float* __restrict__ o_seq, float* __restrict__ o_prob,
    float* __restrict__ o_mu, float* __restrict__ o_std)
{
    __shared__ Smem s;
    const int cta = blockIdx.x;
    const int tid = threadIdx.x;
    const float LPC = -0.5f * 1.8378770664093453f * (float)Hz;

    // zero recurrent state
    g_h[cta * 512 + tid]       = 0.0f;
    g_h[cta * 512 + tid + 256] = 0.0f;
    grid_sync();

    for (int t = 0; t < Tz; t++) {
        // ---- Phase 0: finalize o_prob(t-1); GEMM1 partial h @ w_hh^T ------
        if (t > 0 && cta < Bz && tid == 0)
            o_prob[cta * Tz + (t - 1)] =
                __ldcg(&g_lpp[cta][0]) + __ldcg(&g_lpp[cta][1]) + LPC;
        {
            const int n0 = (cta & 7) * 128;
            const int sl = cta >> 3;                 // 0..15
            ull acc[4][4] = {};
            gemm_tile<true>(s, g_h, w_hh + (size_t)n0 * 1024,
                            sl * KS, KS, acc);
            store_tile(g_p1 + (size_t)sl * (Bz * Hz), Hz, n0, acc);
        }
        grid_sync();

        // ---- Phase 1: combine + tanh -> g_hrnn -----------------------------
        {
            #pragma unroll
            for (int u = 0; u < 2; u++) {
                int idx = cta * 512 + tid + u * 256;   // b*1024 + j
                int b = idx >> 10, j = idx & 1023;
                float v = __ldg(&g_xw[((size_t)b * Tz + t) * Hz + j]);
                float p[NSLC];
                #pragma unroll
                for (int sl = 0; sl < NSLC; sl++)
                    p[sl] = __ldcg(&g_p1[(size_t)sl * (Bz * Hz) + idx]);
                #pragma unroll
                for (int sl = 0; sl < NSLC; sl++) v += p[sl];
                g_hrnn[idx] = tanhf(v);
            }
        }
        grid_sync();

        // ---- Phase 2: GEMM2 partial h_rnn @ w_g^T (2 works/CTA) ------------
        {
            #pragma unroll
            for (int w = 0; w < 2; w++) {
                int work = cta + w * 128;             // 0..255
                int n0 = (work & 15) * 128;
                int sl = work >> 4;                   // 0..15
                ull acc[4][4] = {};
                gemm_tile<true>(s, g_hrnn, w_g + (size_t)n0 * 1024,
                                sl * KS, KS, acc);
                store_tile(g_p2 + (size_t)sl * (Bz * H2z), H2z, n0, acc);
            }
        }
        grid_sync();

        // ---- Phase 3: epilogue, half batch-row per CTA ---------------------
        {
            const int b = cta >> 1;
            const int jb = (cta & 1) * 512;
            float lp = 0.0f;
            #pragma unroll
            for (int u = 0; u < 2; u++) {
                int j = jb + tid + u * 256;
                float ss = __ldg(&b_g[j]);
                float sm = __ldg(&b_g[Hz + j]);
                #pragma unroll
                for (int sl = 0; sl < NSLC; sl++) {
                    const float* p = g_p2 + (size_t)sl * (Bz * H2z)
                                   + (size_t)b * H2z;
                    ss += __ldcg(&p[j]);
                    sm += __ldcg(&p[Hz + j]);
                }
                float sd = (ss > 20.0f) ? ss : log1pf(expf(ss));
                float e = __ldg(&eps[((size_t)b * Tz + t) * Hz + j]);
                float sample = sm + sd * e;
                size_t o = ((size_t)b * Tz + t) * Hz + j;
                o_seq[o] = sample;
                o_mu[o]  = sm;
                o_std[o] = sd;
                g_h[b * Hz + j] = sample;
                lp += -0.5f * e * e - logf(sd);
            }
            #pragma unroll
            for (int o = 16; o > 0; o >>= 1)
                lp += __shfl_xor_sync(0xffffffffu, lp, o);
            __shared__ float red[8];
            if ((tid & 31) == 0) red[tid >> 5] = lp;
            __syncthreads();
            if (tid == 0) {
                float sum = 0.0f;
                #pragma unroll
                for (int w = 0; w < 8; w++) sum += red[w];
                g_lpp[b][cta & 1] = sum;
            }
        }
        grid_sync();
    }

    // final o_prob for t = 511
    if (cta < Bz && tid == 0)
        o_prob[cta * Tz + (Tz - 1)] =
            __ldcg(&g_lpp[cta][0]) + __ldcg(&g_lpp[cta][1]) + LPC;
}

// ---------------------------------------------------------------------------
extern "C" void kernel_launch(void* const* d_in, const int* in_sizes, int n_in,
                              void* d_out, int out_size)
{
    const float* x    = (const float*)d_in[0];
    const float* eps  = (const float*)d_in[1];
    const float* w_ih = (const float*)d_in[2];
    const float* w_hh = (const float*)d_in[3];
    const float* b_ih = (const float*)d_in[4];
    const float* b_hh = (const float*)d_in[5];
    const float* w_g  = (const float*)d_in[6];
    const float* b_g  = (const float*)d_in[7];

    float* out = (float*)d_out;
    float* o_seq  = out;
    float* o_prob = out + (size_t)Bz * Tz * Hz;
    float* o_mu   = o_prob + (size_t)Bz * Tz;
    float* o_std  = o_mu + (size_t)Bz * Tz * Hz;

    xw_kernel<<<dim3(8, 512), 256>>>(x, w_ih, b_ih, b_hh);
    rnn_persistent<<<NCTA, 256>>>(eps, w_hh, w_g, b_g,
                                  o_seq, o_prob, o_mu, o_std);
}